// round 15
// baseline (speedup 1.0000x reference)
#include <cuda_runtime.h>
#include <cuda_fp16.h>
#include <cstdint>

// ============================================================================
// SubtractionGaussian: out[b,h,i,j] = ||q_i||^2 + ||k_j||^2 - 2 q_i . k_j
// B*H = 32, Lq = Lk = 2048, D = 64, fp32 in/out.
//
// R15 = R11 engine (32x64 fp16-acc warp tiles, 80 regs, 3 CTAs/SM target)
//     + R14 region (256x256 CTA, loads amortized 2x both sides, 4 subtiles)
//     + XOR-swizzled unpadded smem (Qs 32KB, Ks 32KB) so 3 CTAs fit:
//       phys_byte = row*ROWB + (col_byte ^ ((row&7)<<4)); all access
//       patterns verified conflict-free (ldmatrix A/B, STS Q/K).
//     smem/CTA = 76800 B; 3x(76800+1024) = 233472 = SM budget exactly.
// ============================================================================

#define LQ 2048
#define LK 2048
#define DDIM 64
#define TM 256
#define TN 256
#define SUB 128
#define THREADS 256

#define QROWB 128       // bytes per Qs row (64 halfs, swizzled)
#define KROWB 512       // bytes per Ks row (256 halfs, swizzled)
#define SWORDS 72       // stage super-row pitch in words (== 8 mod 32 -> STS conflict-free)

// dynamic smem layout (bytes)
#define OFF_QS   0                        // 256*128  = 32768
#define OFF_KS   32768                    // 64*512   = 32768
#define OFF_STG  65536                    // 8 warps * 1152B = 9216 (kpart aliases here)
#define OFF_Q2   74752                    // 256*4    = 1024
#define OFF_K2   75776                    // 256*4    = 1024
#define SMEM_TOTAL 76800

#define SWZ(b, r) ((b) ^ (((r) & 7) << 4))

// f16-accum MMA: D,C are 2 regs of half2. Chained D=C.
__device__ __forceinline__ void mma16816_f16(uint32_t* d, const uint32_t* a,
                                             uint32_t b0, uint32_t b1) {
    asm volatile(
        "mma.sync.aligned.m16n8k16.row.col.f16.f16.f16.f16 "
        "{%0,%1}, {%2,%3,%4,%5}, {%6,%7}, {%0,%1};"
        : "+r"(d[0]), "+r"(d[1])
        : "r"(a[0]), "r"(a[1]), "r"(a[2]), "r"(a[3]), "r"(b0), "r"(b1));
}

__device__ __forceinline__ void ldmatrix_x4(uint32_t* r, uint32_t addr) {
    asm volatile("ldmatrix.sync.aligned.m8n8.x4.shared.b16 {%0,%1,%2,%3}, [%4];"
                 : "=r"(r[0]), "=r"(r[1]), "=r"(r[2]), "=r"(r[3]) : "r"(addr));
}

__device__ __forceinline__ void ldmatrix_x4_trans(uint32_t* r, uint32_t addr) {
    asm volatile("ldmatrix.sync.aligned.m8n8.x4.trans.shared.b16 {%0,%1,%2,%3}, [%4];"
                 : "=r"(r[0]), "=r"(r[1]), "=r"(r[2]), "=r"(r[3]) : "r"(addr));
}

__global__ void __launch_bounds__(THREADS, 3)
subgauss_kernel(const float* __restrict__ q,   // [BH, Lq, D]
                const float* __restrict__ k,   // [BH, D, Lk]
                float* __restrict__ out)       // [BH, Lq, Lk]
{
    extern __shared__ __align__(16) char smem[];
    char* QsB = smem + OFF_QS;                                   // swizzled [256][128B]
    char* KsB = smem + OFF_KS;                                   // swizzled [64][512B], holds -2k
    uint32_t* stgall = reinterpret_cast<uint32_t*>(smem + OFF_STG);
    float* kpart = reinterpret_cast<float*>(smem + OFF_STG);     // alias: dead before stage use
    float* q2s = reinterpret_cast<float*>(smem + OFF_Q2);        // [TM]
    float* k2s = reinterpret_cast<float*>(smem + OFF_K2);        // [TN]

    const int tid = threadIdx.x;
    const int lane = tid & 31;
    const int wid = tid >> 5;

    const int bh = blockIdx.z;
    const int i0 = blockIdx.y * TM;
    const int j0 = blockIdx.x * TN;

    // ---- Q load: 256 rows; 2 rows per warp-inst (16 lanes x float4). ----
    {
        const int hi = lane >> 4;
        const int seg2 = lane & 15;
#pragma unroll
        for (int p = 0; p < 16; p++) {
            const int r = wid * 2 + hi + p * 16;
            const float* qrow = q + ((size_t)bh * LQ + (size_t)(i0 + r)) * DDIM;
            float4 v = *reinterpret_cast<const float4*>(qrow + seg2 * 4);
            float s = v.x * v.x + v.y * v.y + v.z * v.z + v.w * v.w;
            s += __shfl_down_sync(0xffffffffu, s, 8, 16);
            s += __shfl_down_sync(0xffffffffu, s, 4, 16);
            s += __shfl_down_sync(0xffffffffu, s, 2, 16);
            s += __shfl_down_sync(0xffffffffu, s, 1, 16);
            if (seg2 == 0) q2s[r] = s;
            __half2 h01 = __floats2half2_rn(v.x, v.y);
            __half2 h23 = __floats2half2_rn(v.z, v.w);
            uint2 u;
            u.x = *reinterpret_cast<uint32_t*>(&h01);
            u.y = *reinterpret_cast<uint32_t*>(&h23);
            *reinterpret_cast<uint2*>(QsB + r * QROWB + SWZ(seg2 * 8, r)) = u;
        }
    }

    // ---- K load: 256 cols (two halves); Ks holds -2k; exact fp32 k2 partials. ----
#pragma unroll
    for (int jt = 0; jt < 2; jt++) {
        const float* kb = k + (size_t)bh * DDIM * LK + (size_t)(j0 + jt * SUB) + lane * 4;
        float4 ksum = make_float4(0.f, 0.f, 0.f, 0.f);
#pragma unroll
        for (int p = 0; p < 8; p++) {
            const int c = wid + p * 8;
            float4 v = *reinterpret_cast<const float4*>(kb + (size_t)c * LK);
            ksum.x += v.x * v.x; ksum.y += v.y * v.y;
            ksum.z += v.z * v.z; ksum.w += v.w * v.w;
            __half2 h01 = __floats2half2_rn(-2.0f * v.x, -2.0f * v.y);
            __half2 h23 = __floats2half2_rn(-2.0f * v.z, -2.0f * v.w);
            uint2 u;
            u.x = *reinterpret_cast<uint32_t*>(&h01);
            u.y = *reinterpret_cast<uint32_t*>(&h23);
            *reinterpret_cast<uint2*>(
                KsB + c * KROWB + SWZ(jt * 256 + lane * 8, c)) = u;
        }
        *reinterpret_cast<float4*>(&kpart[wid * TN + jt * SUB + lane * 4]) = ksum;
    }
    __syncthreads();

    // ---- k2 reduce: 256 threads, exact fp32 (kpart region dies here). ----
    {
        float s = 0.0f;
#pragma unroll
        for (int w = 0; w < 8; w++) s += kpart[w * TN + tid];
        k2s[tid] = s;
    }
    __syncthreads();
    // -------- no CTA-wide barriers below this line --------

    // ---- Warp tile 32x64: 4 M-groups x 2 N-groups per 128x128 subtile. ----
    const int wm = wid & 3;
    const int wn = wid >> 2;
    const int mbase = wm * 32;
    const int nbase = wn * 64;
    const int g = lane >> 3;      // ldmatrix quadrant
    const int lr = lane & 7;      // ldmatrix row

    uint32_t* stgW = stgall + wid * 4 * SWORDS;   // warp-private stage
    // writer roles
    const int tq = lane & 3;
    const int sw = (lane >> 2) >> 1;     // super-row
    const int e0 = (lane >> 2) & 1;      // row parity
    const uint32_t psel = e0 ? 0x3276u : 0x5410u;
    // reader roles
    const int sr = lane >> 3;
    const int j8 = lane & 7;

#pragma unroll 1
    for (int it = 0; it < 2; it++) {
#pragma unroll 1
        for (int jt = 0; jt < 2; jt++) {
            uint32_t acc[2][8][2];
#pragma unroll
            for (int mm = 0; mm < 2; mm++)
#pragma unroll
                for (int nn = 0; nn < 8; nn++) {
                    acc[mm][nn][0] = 0u;
                    acc[mm][nn][1] = 0u;
                }

            // ---- Mainloop: fp16 accumulate; acc = -2*q.k (K pre-scaled). ----
#pragma unroll
            for (int ks = 0; ks < 4; ks++) {
                uint32_t A[2][4];
#pragma unroll
                for (int mm = 0; mm < 2; mm++) {
                    const int R = it * SUB + mbase + mm * 16 + (g & 1) * 8 + lr;
                    uint32_t addr = (uint32_t)__cvta_generic_to_shared(
                        QsB + R * QROWB + SWZ(ks * 32 + (g >> 1) * 16, R));
                    ldmatrix_x4(A[mm], addr);
                }
#pragma unroll
                for (int e = 0; e < 4; e++) {
                    const int C = ks * 16 + (g & 1) * 8 + lr;
                    uint32_t B[4];
                    uint32_t addr = (uint32_t)__cvta_generic_to_shared(
                        KsB + C * KROWB +
                        SWZ(jt * 256 + nbase * 2 + e * 32 + (g >> 1) * 16, C));
                    ldmatrix_x4_trans(B, addr);
                    mma16816_f16(acc[0][2 * e],     A[0], B[0], B[1]);
                    mma16816_f16(acc[1][2 * e],     A[1], B[0], B[1]);
                    mma16816_f16(acc[0][2 * e + 1], A[0], B[2], B[3]);
                    mma16816_f16(acc[1][2 * e + 1], A[1], B[2], B[3]);
                }
            }

            // ---- Epilogue: fp16 interleaved stage, 4 slabs (mm x h). ----
            float4 k2A = *reinterpret_cast<const float4*>(
                &k2s[jt * SUB + nbase + j8 * 4]);
            float4 k2B = *reinterpret_cast<const float4*>(
                &k2s[jt * SUB + nbase + 32 + j8 * 4]);

#pragma unroll
            for (int mm = 0; mm < 2; mm++) {
#pragma unroll
                for (int h = 0; h < 2; h++) {
                    const int rowb = it * SUB + mbase + mm * 16 + h * 8;
                    __syncwarp();
                    // writer: row-pair interleave via shfl.xor(4) + PRMT, STS.32
#pragma unroll
                    for (int nn = 0; nn < 8; nn++) {
                        uint32_t own = acc[mm][nn][h];
                        uint32_t rp = __shfl_xor_sync(0xffffffffu, own, 4);
                        uint32_t mrg = __byte_perm(own, rp, psel);
                        stgW[sw * SWORDS + 8 * nn + 2 * tq + e0] = mrg;
                    }
                    __syncwarp();
                    // q2 for this slab's row pair
                    const float q2e = q2s[rowb + 2 * sr];
                    const float q2o = q2s[rowb + 2 * sr + 1];
                    // reader: 2x LDS.128 -> cvt -> 4x STG.128 (4 rows x 128B dense)
#pragma unroll
                    for (int L = 0; L < 2; L++) {
                        uint4 w = *reinterpret_cast<const uint4*>(
                            &stgW[sr * SWORDS + (j8 + 8 * L) * 4]);
                        float2 c0 = __half22float2(*reinterpret_cast<__half2*>(&w.x));
                        float2 c1 = __half22float2(*reinterpret_cast<__half2*>(&w.y));
                        float2 c2 = __half22float2(*reinterpret_cast<__half2*>(&w.z));
                        float2 c3 = __half22float2(*reinterpret_cast<__half2*>(&w.w));
                        const float4 k2v = L ? k2B : k2A;
                        float4 oe, oo;
                        oe.x = q2e + k2v.x + c0.x;
                        oe.y = q2e + k2v.y + c1.x;
                        oe.z = q2e + k2v.z + c2.x;
                        oe.w = q2e + k2v.w + c3.x;
                        oo.x = q2o + k2v.x + c0.y;
                        oo.y = q2o + k2v.y + c1.y;
                        oo.z = q2o + k2v.z + c2.y;
                        oo.w = q2o + k2v.w + c3.y;
                        const size_t rbase = (size_t)bh * LQ +
                                             (size_t)(i0 + rowb + 2 * sr);
                        const int cg = j0 + jt * SUB + nbase + 32 * L + 4 * j8;
                        *reinterpret_cast<float4*>(out + rbase * LK + cg) = oe;
                        *reinterpret_cast<float4*>(out + (rbase + 1) * LK + cg) = oo;
                    }
                }
            }
        }
    }
}

// ---------------- Launch ----------------

extern "C" void kernel_launch(void* const* d_in, const int* in_sizes, int n_in,
                              void* d_out, int out_size) {
    const float* q = (const float*)d_in[0];   // [4,8,2048,64]
    const float* k = (const float*)d_in[1];   // [4,8,64,2048]
    float* out = (float*)d_out;               // [4,8,2048,2048]
    (void)in_sizes; (void)n_in; (void)out_size;

    cudaFuncSetAttribute(subgauss_kernel,
                         cudaFuncAttributeMaxDynamicSharedMemorySize, SMEM_TOTAL);

    dim3 grid(LK / TN, LQ / TM, 32);  // 8 x 8 x 32
    subgauss_kernel<<<grid, THREADS, SMEM_TOTAL>>>(q, k, out);
}

// round 16
// speedup vs baseline: 1.5145x; 1.5145x over previous
#include <cuda_runtime.h>
#include <cuda_fp16.h>
#include <cstdint>

// ============================================================================
// SubtractionGaussian: out[b,h,i,j] = ||q_i||^2 + ||k_j||^2 - 2 q_i . k_j
// B*H = 32, Lq = Lk = 2048, D = 64, fp32 in/out.
//
// R16 = R11 (proven 109.1us: fp16 accumulators, 32x64 warp tiles, 3 CTAs/SM,
//       TM=128 x TN=256, padded smem, fp16 interleaved-stage epilogue)
//     + st.global.cs streaming stores on the write-once output.
// R12-R15 post-mortems: 64x64 tiles / pipelined epilogues / XOR-swizzled smem
//       all neutral-or-worse; R11 is the empirical optimum at 24-warp L1
//       saturation (~87%).
// ============================================================================

#define LQ 2048
#define LK 2048
#define DDIM 64
#define TM 128
#define TN 256
#define SUBN 128
#define THREADS 256

#define QROW 72         // halfs per Qs row (9 granules == 1 mod 8 -> ldmatrix conflict-free)
#define KROW 264        // halfs per Ks row (33 granules == 1 mod 8 -> conflict-free)
#define SWORDS 72       // stage super-row pitch in words (== 8 mod 32 -> STS conflict-free)

// dynamic smem layout (bytes)
#define OFF_QS   0                        // 128*72*2  = 18432
#define OFF_KS   18432                    // 64*264*2  = 33792
#define OFF_STG  52224                    // 8 warps * 1152B = 9216 (kpart aliases here)
#define OFF_Q2   61440                    // 128*4     = 512
#define OFF_K2   61952                    // 256*4     = 1024
#define SMEM_TOTAL 62976

// f16-accum MMA: D,C are 2 regs of half2. Chained D=C.
__device__ __forceinline__ void mma16816_f16(uint32_t* d, const uint32_t* a,
                                             uint32_t b0, uint32_t b1) {
    asm volatile(
        "mma.sync.aligned.m16n8k16.row.col.f16.f16.f16.f16 "
        "{%0,%1}, {%2,%3,%4,%5}, {%6,%7}, {%0,%1};"
        : "+r"(d[0]), "+r"(d[1])
        : "r"(a[0]), "r"(a[1]), "r"(a[2]), "r"(a[3]), "r"(b0), "r"(b1));
}

__device__ __forceinline__ void ldmatrix_x4(uint32_t* r, uint32_t addr) {
    asm volatile("ldmatrix.sync.aligned.m8n8.x4.shared.b16 {%0,%1,%2,%3}, [%4];"
                 : "=r"(r[0]), "=r"(r[1]), "=r"(r[2]), "=r"(r[3]) : "r"(addr));
}

__device__ __forceinline__ void ldmatrix_x4_trans(uint32_t* r, uint32_t addr) {
    asm volatile("ldmatrix.sync.aligned.m8n8.x4.trans.shared.b16 {%0,%1,%2,%3}, [%4];"
                 : "=r"(r[0]), "=r"(r[1]), "=r"(r[2]), "=r"(r[3]) : "r"(addr));
}

// streaming (evict-first) 16B store
__device__ __forceinline__ void stg_cs(float* p, float4 v) {
    asm volatile("st.global.cs.v4.f32 [%0], {%1, %2, %3, %4};"
                 :: "l"(p), "f"(v.x), "f"(v.y), "f"(v.z), "f"(v.w) : "memory");
}

__global__ void __launch_bounds__(THREADS, 3)
subgauss_kernel(const float* __restrict__ q,   // [BH, Lq, D]
                const float* __restrict__ k,   // [BH, D, Lk]
                float* __restrict__ out)       // [BH, Lq, Lk]
{
    extern __shared__ __align__(16) char smem[];
    __half* Qs = reinterpret_cast<__half*>(smem + OFF_QS);       // [TM][QROW]
    __half* Ks = reinterpret_cast<__half*>(smem + OFF_KS);       // [DDIM][KROW], holds -2k
    uint32_t* stgall = reinterpret_cast<uint32_t*>(smem + OFF_STG);
    float* kpart = reinterpret_cast<float*>(smem + OFF_STG);     // alias: dead before stage use
    float* q2s = reinterpret_cast<float*>(smem + OFF_Q2);        // [TM]
    float* k2s = reinterpret_cast<float*>(smem + OFF_K2);        // [TN]

    const int tid = threadIdx.x;
    const int lane = tid & 31;
    const int wid = tid >> 5;

    const int bh = blockIdx.z;
    const int i0 = blockIdx.y * TM;
    const int j0 = blockIdx.x * TN;

    // ---- Q load: 128 rows; 2 rows per warp-inst (16 lanes x float4). ----
    {
        const int hi = lane >> 4;
        const int seg2 = lane & 15;
#pragma unroll
        for (int p = 0; p < 8; p++) {
            const int r = wid * 2 + hi + p * 16;
            const float* qrow = q + ((size_t)bh * LQ + (size_t)(i0 + r)) * DDIM;
            float4 v = *reinterpret_cast<const float4*>(qrow + seg2 * 4);
            float s = v.x * v.x + v.y * v.y + v.z * v.z + v.w * v.w;
            s += __shfl_down_sync(0xffffffffu, s, 8, 16);
            s += __shfl_down_sync(0xffffffffu, s, 4, 16);
            s += __shfl_down_sync(0xffffffffu, s, 2, 16);
            s += __shfl_down_sync(0xffffffffu, s, 1, 16);
            if (seg2 == 0) q2s[r] = s;
            __half2 h01 = __floats2half2_rn(v.x, v.y);
            __half2 h23 = __floats2half2_rn(v.z, v.w);
            uint2 u;
            u.x = *reinterpret_cast<uint32_t*>(&h01);
            u.y = *reinterpret_cast<uint32_t*>(&h23);
            *reinterpret_cast<uint2*>(&Qs[r * QROW + seg2 * 4]) = u;
        }
    }

    // ---- K load: 256 cols (two halves); Ks holds -2k; exact fp32 k2 partials. ----
#pragma unroll
    for (int jt = 0; jt < 2; jt++) {
        const float* kb = k + (size_t)bh * DDIM * LK + (size_t)(j0 + jt * SUBN) + lane * 4;
        float4 ksum = make_float4(0.f, 0.f, 0.f, 0.f);
#pragma unroll
        for (int p = 0; p < 8; p++) {
            const int c = wid + p * 8;
            float4 v = *reinterpret_cast<const float4*>(kb + (size_t)c * LK);
            ksum.x += v.x * v.x; ksum.y += v.y * v.y;
            ksum.z += v.z * v.z; ksum.w += v.w * v.w;
            __half2 h01 = __floats2half2_rn(-2.0f * v.x, -2.0f * v.y);
            __half2 h23 = __floats2half2_rn(-2.0f * v.z, -2.0f * v.w);
            uint2 u;
            u.x = *reinterpret_cast<uint32_t*>(&h01);
            u.y = *reinterpret_cast<uint32_t*>(&h23);
            *reinterpret_cast<uint2*>(&Ks[c * KROW + jt * SUBN + lane * 4]) = u;
        }
        *reinterpret_cast<float4*>(&kpart[wid * TN + jt * SUBN + lane * 4]) = ksum;
    }
    __syncthreads();

    // ---- k2 reduce: 256 threads, exact fp32 (kpart region dies here). ----
    {
        float s = 0.0f;
#pragma unroll
        for (int w = 0; w < 8; w++) s += kpart[w * TN + tid];
        k2s[tid] = s;
    }
    __syncthreads();
    // -------- no CTA-wide barriers below this line --------

    const int wm = wid & 3;
    const int wn = wid >> 2;
    const int mbase = wm * 32;
    const int nbase = wn * 64;
    const int g = lane >> 3;      // ldmatrix quadrant
    const int lr = lane & 7;      // ldmatrix row

    uint32_t* stgW = stgall + wid * 4 * SWORDS;   // warp-private stage
    // writer roles
    const int tq = lane & 3;
    const int sw = (lane >> 2) >> 1;     // super-row
    const int e0 = (lane >> 2) & 1;      // row parity
    const uint32_t psel = e0 ? 0x3276u : 0x5410u;
    // reader roles
    const int sr = lane >> 3;
    const int j8 = lane & 7;

    // q2 rows fixed across jt: preload 8 values (mm,h,parity)
    float q2r[8];
#pragma unroll
    for (int mm = 0; mm < 2; mm++)
#pragma unroll
        for (int h = 0; h < 2; h++)
#pragma unroll
            for (int p = 0; p < 2; p++)
                q2r[mm * 4 + h * 2 + p] = q2s[mbase + mm * 16 + h * 8 + 2 * sr + p];

#pragma unroll 1
    for (int jt = 0; jt < 2; jt++) {
        uint32_t acc[2][8][2];
#pragma unroll
        for (int mm = 0; mm < 2; mm++)
#pragma unroll
            for (int nn = 0; nn < 8; nn++) {
                acc[mm][nn][0] = 0u;
                acc[mm][nn][1] = 0u;
            }

        // ---- Mainloop: fp16 accumulate; acc = -2*q.k (K pre-scaled). ----
#pragma unroll
        for (int ks = 0; ks < 4; ks++) {
            uint32_t A[2][4];
#pragma unroll
            for (int mm = 0; mm < 2; mm++) {
                uint32_t addr = (uint32_t)__cvta_generic_to_shared(
                    &Qs[(mbase + mm * 16 + (g & 1) * 8 + lr) * QROW
                        + ks * 16 + (g >> 1) * 8]);
                ldmatrix_x4(A[mm], addr);
            }
#pragma unroll
            for (int e = 0; e < 4; e++) {
                uint32_t B[4];
                uint32_t addr = (uint32_t)__cvta_generic_to_shared(
                    &Ks[(ks * 16 + (g & 1) * 8 + lr) * KROW
                        + jt * SUBN + nbase + e * 16 + (g >> 1) * 8]);
                ldmatrix_x4_trans(B, addr);
                mma16816_f16(acc[0][2 * e],     A[0], B[0], B[1]);
                mma16816_f16(acc[1][2 * e],     A[1], B[0], B[1]);
                mma16816_f16(acc[0][2 * e + 1], A[0], B[2], B[3]);
                mma16816_f16(acc[1][2 * e + 1], A[1], B[2], B[3]);
            }
        }

        // ---- Epilogue: acc word IS the stage payload (no cvt, no mul). ----
        float4 k2A = *reinterpret_cast<const float4*>(&k2s[jt * SUBN + nbase + j8 * 4]);
        float4 k2B = *reinterpret_cast<const float4*>(&k2s[jt * SUBN + nbase + 32 + j8 * 4]);

#pragma unroll
        for (int mm = 0; mm < 2; mm++) {
#pragma unroll
            for (int h = 0; h < 2; h++) {
                __syncwarp();
                // writer: row-pair interleave via shfl.xor(4) + PRMT, STS.32
#pragma unroll
                for (int nn = 0; nn < 8; nn++) {
                    uint32_t own = acc[mm][nn][h];
                    uint32_t rp = __shfl_xor_sync(0xffffffffu, own, 4);
                    uint32_t mrg = __byte_perm(own, rp, psel);
                    stgW[sw * SWORDS + 8 * nn + 2 * tq + e0] = mrg;
                }
                __syncwarp();
                // reader: 2x LDS.128 -> cvt -> 4x STG.128 (4 rows x 128B dense)
#pragma unroll
                for (int L = 0; L < 2; L++) {
                    uint4 w = *reinterpret_cast<const uint4*>(
                        &stgW[sr * SWORDS + (j8 + 8 * L) * 4]);
                    float2 c0 = __half22float2(*reinterpret_cast<__half2*>(&w.x));
                    float2 c1 = __half22float2(*reinterpret_cast<__half2*>(&w.y));
                    float2 c2 = __half22float2(*reinterpret_cast<__half2*>(&w.z));
                    float2 c3 = __half22float2(*reinterpret_cast<__half2*>(&w.w));
                    const float4 k2v = L ? k2B : k2A;
                    const float q2e = q2r[mm * 4 + h * 2 + 0];
                    const float q2o = q2r[mm * 4 + h * 2 + 1];
                    float4 oe, oo;
                    oe.x = q2e + k2v.x + c0.x;
                    oe.y = q2e + k2v.y + c1.x;
                    oe.z = q2e + k2v.z + c2.x;
                    oe.w = q2e + k2v.w + c3.x;
                    oo.x = q2o + k2v.x + c0.y;
                    oo.y = q2o + k2v.y + c1.y;
                    oo.z = q2o + k2v.z + c2.y;
                    oo.w = q2o + k2v.w + c3.y;
                    const size_t rbase = (size_t)bh * LQ +
                        (size_t)(i0 + mbase + mm * 16 + h * 8 + 2 * sr);
                    const int cg = j0 + jt * SUBN + nbase + 32 * L + 4 * j8;
                    stg_cs(out + rbase * LK + cg, oe);
                    stg_cs(out + (rbase + 1) * LK + cg, oo);
                }
            }
        }
    }
}

// ---------------- Launch ----------------

extern "C" void kernel_launch(void* const* d_in, const int* in_sizes, int n_in,
                              void* d_out, int out_size) {
    const float* q = (const float*)d_in[0];   // [4,8,2048,64]
    const float* k = (const float*)d_in[1];   // [4,8,64,2048]
    float* out = (float*)d_out;               // [4,8,2048,2048]
    (void)in_sizes; (void)n_in; (void)out_size;

    cudaFuncSetAttribute(subgauss_kernel,
                         cudaFuncAttributeMaxDynamicSharedMemorySize, SMEM_TOTAL);

    dim3 grid(LK / TN, LQ / TM, 32);  // 8 x 16 x 32
    subgauss_kernel<<<grid, THREADS, SMEM_TOTAL>>>(q, k, out);
}